// round 3
// baseline (speedup 1.0000x reference)
#include <cuda_runtime.h>
#include <cuda_bf16.h>
#include <math_constants.h>

#define BB 64
#define SS 4096
#define DD 256
#define CHUNK 32
#define NCHUNK (SS / CHUNK)   // 128
#define CGROUPS 16            // combine blocks per batch (each handles 16 d's)

// Scratch (allocation-free: __device__ globals)
__device__ float g_pm[BB * NCHUNK];            // chunk max
__device__ float g_pl[BB * NCHUNK];            // chunk exp-sum
__device__ float g_pa[BB * NCHUNK * DD];       // chunk weighted partials (8 MB)

// ---------------------------------------------------------------------------
// Kernel 1: one block per (b, chunk). 256 threads (8 warps).
//   Front-batched loads (MLP=8/warp), pipelined shuffle reductions.
// ---------------------------------------------------------------------------
__global__ __launch_bounds__(256) void ta_partial_kernel(
    const float* __restrict__ enc,   // [B, S, D]
    const float* __restrict__ Ww,    // [1, D]
    const float* __restrict__ ut)    // [1, 1]
{
    __shared__ float sx[CHUNK][DD];  // 32 KB tile
    __shared__ float ssc[CHUNK];     // scores -> exp weights

    const int blk  = blockIdx.x;
    const int b    = blk >> 7;       // / NCHUNK
    const int c    = blk & (NCHUNK - 1);
    const int tid  = threadIdx.x;
    const int w    = tid >> 5;
    const int lane = tid & 31;

    const float u = ut[0];

    // per-lane weight fragments: d = 4*lane + {0..3} and 128 + 4*lane + {0..3}
    const float4 w0 = reinterpret_cast<const float4*>(Ww)[lane];
    const float4 w1 = reinterpret_cast<const float4*>(Ww)[lane + 32];

    const float4* base4 =
        reinterpret_cast<const float4*>(enc + ((size_t)b * SS + (size_t)c * CHUNK) * DD);

    // ---- Phase 1a: front-batch ALL 8 LDG.128 (rows sl = w + 8i) ----
    float4 a[4][2];
    #pragma unroll
    for (int i = 0; i < 4; i++) {
        const int sl = w + 8 * i;
        a[i][0] = base4[sl * 64 + lane];
        a[i][1] = base4[sl * 64 + lane + 32];
    }

    // ---- Phase 1b: stage to smem ----
    #pragma unroll
    for (int i = 0; i < 4; i++) {
        const int sl = w + 8 * i;
        reinterpret_cast<float4*>(&sx[sl][0])[lane]      = a[i][0];
        reinterpret_cast<float4*>(&sx[sl][0])[lane + 32] = a[i][1];
    }

    // ---- Phase 1c: 4 independent dot partials ----
    float p[4];
    #pragma unroll
    for (int i = 0; i < 4; i++) {
        float x = a[i][0].x * w0.x;
        float y = a[i][0].y * w0.y;
        x = fmaf(a[i][0].z, w0.z, x);
        y = fmaf(a[i][0].w, w0.w, y);
        x = fmaf(a[i][1].x, w1.x, x);
        y = fmaf(a[i][1].y, w1.y, y);
        x = fmaf(a[i][1].z, w1.z, x);
        y = fmaf(a[i][1].w, w1.w, y);
        p[i] = x + y;
    }

    // ---- Phase 1d: pipelined shuffle reduction (4 trees interleaved) ----
    #pragma unroll
    for (int off = 16; off > 0; off >>= 1) {
        #pragma unroll
        for (int i = 0; i < 4; i++)
            p[i] += __shfl_xor_sync(0xffffffffu, p[i], off);
    }
    if (lane == 0) {
        #pragma unroll
        for (int i = 0; i < 4; i++)
            ssc[w + 8 * i] = p[i];
    }
    __syncthreads();

    // ---- Phase 2: warp 0 computes chunk-local softmax numerators ----
    if (w == 0) {
        float v = u * ssc[lane];
        float m = v;
        #pragma unroll
        for (int off = 16; off > 0; off >>= 1)
            m = fmaxf(m, __shfl_xor_sync(0xffffffffu, m, off));
        const float e = __expf(v - m);
        float l = e;
        #pragma unroll
        for (int off = 16; off > 0; off >>= 1)
            l += __shfl_xor_sync(0xffffffffu, l, off);
        ssc[lane] = e;
        if (lane == 0) {
            g_pm[b * NCHUNK + c] = m;
            g_pl[b * NCHUNK + c] = l;
        }
    }
    __syncthreads();

    // ---- Phase 3: weighted accumulate (conflict-free smem columns) ----
    float acc = 0.f;
    #pragma unroll
    for (int s = 0; s < CHUNK; s++)
        acc = fmaf(ssc[s], sx[s][tid], acc);

    g_pa[((size_t)(b * NCHUNK + c)) * DD + tid] = acc;
}

// ---------------------------------------------------------------------------
// Kernel 2: grid = BB * CGROUPS. Block (b, g) handles d in [g*16, g*16+16).
//   256 threads = 16 chunk-lanes x 16 d-lanes; each sums 8 strided partials.
// ---------------------------------------------------------------------------
__global__ __launch_bounds__(256) void ta_combine_kernel(float* __restrict__ out)
{
    __shared__ float red[128];
    __shared__ float wsc[NCHUNK];
    __shared__ float acc2[16][17];   // +1 pad: column reads conflict-free

    const int b = blockIdx.x >> 4;
    const int g = blockIdx.x & 15;
    const int t = threadIdx.x;
    const int ci = t >> 4;       // 0..15
    const int dl = t & 15;
    const int d  = g * 16 + dl;

    // --- M = max over 128 chunk maxima ---
    if (t < NCHUNK) red[t] = g_pm[b * NCHUNK + t];
    __syncthreads();
    if (t < 64) red[t] = fmaxf(red[t], red[t + 64]);
    __syncthreads();
    if (t < 32) {
        float m = fmaxf(red[t], red[t + 32]);
        #pragma unroll
        for (int off = 16; off > 0; off >>= 1)
            m = fmaxf(m, __shfl_xor_sync(0xffffffffu, m, off));
        if (t == 0) red[0] = m;
    }
    __syncthreads();
    const float M = red[0];
    __syncthreads();

    // --- L = sum exp(m_c - M) * l_c ; stash numerators in wsc ---
    if (t < NCHUNK) {
        const float e = __expf(g_pm[b * NCHUNK + t] - M);
        wsc[t] = e;
        red[t] = e * g_pl[b * NCHUNK + t];
    }
    __syncthreads();
    if (t < 64) red[t] += red[t + 64];
    __syncthreads();
    if (t < 32) {
        float l = red[t] + red[t + 32];
        #pragma unroll
        for (int off = 16; off > 0; off >>= 1)
            l += __shfl_xor_sync(0xffffffffu, l, off);
        if (t == 0) red[0] = l;
    }
    __syncthreads();
    const float Linv = 1.0f / red[0];

    // --- weighted partial sum: thread (ci, dl) covers chunks ci, ci+16, ... ---
    float acc = 0.f;
    #pragma unroll
    for (int i = 0; i < NCHUNK / 16; i++) {
        const int c = ci + 16 * i;
        acc = fmaf(wsc[c], g_pa[((size_t)(b * NCHUNK + c)) * DD + d], acc);
    }
    acc2[ci][dl] = acc;
    __syncthreads();

    // --- reduce 16 chunk-lanes: warp 0 threads each own one d ---
    if (t < 16) {
        float o = 0.f;
        #pragma unroll
        for (int i = 0; i < 16; i++)
            o += acc2[i][t];
        out[(g * 16 + t) * BB + b] = o * Linv;   // out is [D, B]
    }
}

extern "C" void kernel_launch(void* const* d_in, const int* in_sizes, int n_in,
                              void* d_out, int out_size)
{
    const float* enc = (const float*)d_in[0];   // [B, S, D]
    const float* Ww  = (const float*)d_in[1];   // [1, D]
    // d_in[2] = We_b : scalar bias is softmax-invariant, dropped
    const float* ut  = (const float*)d_in[3];   // [1, 1]
    float* out = (float*)d_out;                 // [D, B]

    ta_partial_kernel<<<BB * NCHUNK, 256>>>(enc, Ww, ut);
    ta_combine_kernel<<<BB * CGROUPS, 256>>>(out);
}

// round 4
// speedup vs baseline: 1.1964x; 1.1964x over previous
#include <cuda_runtime.h>
#include <cuda_bf16.h>
#include <math_constants.h>
#include <cstdint>

#define BB 64
#define SS 4096
#define DD 256
#define CHUNK 32
#define NCHUNK (SS / CHUNK)   // 128
#define TILE_BYTES (CHUNK * DD * 4)  // 32 KB

// Scratch (allocation-free: __device__ globals)
__device__ float g_pm[BB * NCHUNK];            // chunk max
__device__ float g_pl[BB * NCHUNK];            // chunk exp-sum
__device__ float g_w [BB * NCHUNK];            // normalized chunk weights
__device__ float g_pa[BB * NCHUNK * DD];       // chunk weighted partials (8 MB)

__device__ __forceinline__ uint32_t smem_u32(const void* p) {
    uint32_t a;
    asm("{ .reg .u64 t; cvta.to.shared.u64 t, %1; cvt.u32.u64 %0, t; }"
        : "=r"(a) : "l"(p));
    return a;
}

__device__ __forceinline__ void mbar_wait(uint32_t mbar, uint32_t parity) {
    asm volatile(
        "{\n\t"
        ".reg .pred P;\n\t"
        "WAIT_%=:\n\t"
        "mbarrier.try_wait.parity.acquire.cta.shared::cta.b64 P, [%0], %1, 0x989680;\n\t"
        "@P bra.uni DONE_%=;\n\t"
        "bra.uni WAIT_%=;\n\t"
        "DONE_%=:\n\t"
        "}" :: "r"(mbar), "r"(parity) : "memory");
}

// ---------------------------------------------------------------------------
// Kernel 1: one block per (b, chunk). 256 threads (8 warps).
//   32 KB tile arrives via cp.async.bulk (UBLKCP) into smem; scores + chunk
//   softmax + weighted partials all computed from smem.
// ---------------------------------------------------------------------------
__global__ __launch_bounds__(256) void ta_partial_kernel(
    const float* __restrict__ enc,   // [B, S, D]
    const float* __restrict__ Ww,    // [1, D]
    const float* __restrict__ ut)    // [1, 1]
{
    __shared__ __align__(128) float sx[CHUNK][DD];  // 32 KB tile
    __shared__ float ssc[CHUNK];
    __shared__ __align__(8) unsigned long long mbar;

    const int blk  = blockIdx.x;
    const int b    = blk >> 7;       // / NCHUNK
    const int c    = blk & (NCHUNK - 1);
    const int tid  = threadIdx.x;
    const int w    = tid >> 5;
    const int lane = tid & 31;

    const uint32_t mb = smem_u32(&mbar);
    const uint32_t sdst = smem_u32(&sx[0][0]);

    if (tid == 0) {
        asm volatile("mbarrier.init.shared.b64 [%0], 1;" :: "r"(mb) : "memory");
    }
    __syncthreads();

    if (tid == 0) {
        const float* src = enc + ((size_t)b * SS + (size_t)c * CHUNK) * DD;
        asm volatile("mbarrier.arrive.expect_tx.shared.b64 _, [%0], %1;"
                     :: "r"(mb), "r"((uint32_t)TILE_BYTES) : "memory");
        asm volatile(
            "cp.async.bulk.shared::cta.global.mbarrier::complete_tx::bytes "
            "[%0], [%1], %2, [%3];"
            :: "r"(sdst), "l"(src), "r"((uint32_t)TILE_BYTES), "r"(mb)
            : "memory");
    }

    // Overlap: load weight fragments while TMA streams
    const float u = ut[0];
    const float4 w0 = reinterpret_cast<const float4*>(Ww)[lane];
    const float4 w1 = reinterpret_cast<const float4*>(Ww)[lane + 32];

    mbar_wait(mb, 0);

    // ---- scores: warp w handles rows sl = w + 8i, LDS.128 from smem ----
    float p[4];
    #pragma unroll
    for (int i = 0; i < 4; i++) {
        const int sl = w + 8 * i;
        const float4 a0 = reinterpret_cast<const float4*>(&sx[sl][0])[lane];
        const float4 a1 = reinterpret_cast<const float4*>(&sx[sl][0])[lane + 32];
        float x = a0.x * w0.x;
        float y = a0.y * w0.y;
        x = fmaf(a0.z, w0.z, x);
        y = fmaf(a0.w, w0.w, y);
        x = fmaf(a1.x, w1.x, x);
        y = fmaf(a1.y, w1.y, y);
        x = fmaf(a1.z, w1.z, x);
        y = fmaf(a1.w, w1.w, y);
        p[i] = x + y;
    }
    #pragma unroll
    for (int off = 16; off > 0; off >>= 1) {
        #pragma unroll
        for (int i = 0; i < 4; i++)
            p[i] += __shfl_xor_sync(0xffffffffu, p[i], off);
    }
    if (lane == 0) {
        #pragma unroll
        for (int i = 0; i < 4; i++)
            ssc[w + 8 * i] = p[i];
    }
    __syncthreads();

    // ---- chunk-local softmax numerators (warp 0) ----
    if (w == 0) {
        float v = u * ssc[lane];
        float m = v;
        #pragma unroll
        for (int off = 16; off > 0; off >>= 1)
            m = fmaxf(m, __shfl_xor_sync(0xffffffffu, m, off));
        const float e = __expf(v - m);
        float l = e;
        #pragma unroll
        for (int off = 16; off > 0; off >>= 1)
            l += __shfl_xor_sync(0xffffffffu, l, off);
        ssc[lane] = e;
        if (lane == 0) {
            g_pm[b * NCHUNK + c] = m;
            g_pl[b * NCHUNK + c] = l;
        }
    }
    __syncthreads();

    // ---- weighted accumulate: thread owns column d = tid ----
    float acc0 = 0.f, acc1 = 0.f;
    #pragma unroll
    for (int s = 0; s < CHUNK; s += 2) {
        acc0 = fmaf(ssc[s],     sx[s][tid],     acc0);
        acc1 = fmaf(ssc[s + 1], sx[s + 1][tid], acc1);
    }
    g_pa[((size_t)(b * NCHUNK + c)) * DD + tid] = acc0 + acc1;
}

// ---------------------------------------------------------------------------
// Kernel 1.5: grid = BB, 128 threads. Per-batch M, L and normalized weights:
//   g_w[b][c] = exp(m_c - M) / L
// ---------------------------------------------------------------------------
__global__ __launch_bounds__(128) void ta_ml_kernel()
{
    __shared__ float red[4];

    const int b = blockIdx.x;
    const int t = threadIdx.x;
    const int w = t >> 5;
    const int lane = t & 31;

    const float m = g_pm[b * NCHUNK + t];
    const float l = g_pl[b * NCHUNK + t];

    // block max
    float mm = m;
    #pragma unroll
    for (int off = 16; off > 0; off >>= 1)
        mm = fmaxf(mm, __shfl_xor_sync(0xffffffffu, mm, off));
    if (lane == 0) red[w] = mm;
    __syncthreads();
    const float M = fmaxf(fmaxf(red[0], red[1]), fmaxf(red[2], red[3]));
    __syncthreads();

    const float e = __expf(m - M);

    // block sum of e * l
    float s = e * l;
    #pragma unroll
    for (int off = 16; off > 0; off >>= 1)
        s += __shfl_xor_sync(0xffffffffu, s, off);
    if (lane == 0) red[w] = s;
    __syncthreads();
    const float L = red[0] + red[1] + red[2] + red[3];

    g_w[b * NCHUNK + t] = e / L;
}

// ---------------------------------------------------------------------------
// Kernel 2: grid = BB * 4. Block (b, g) covers d in [g*64, g*64+64) as float4.
//   256 threads = 16 chunk-lanes x 16 float4-lanes. Pure streaming, no
//   reduction preamble.
// ---------------------------------------------------------------------------
__global__ __launch_bounds__(256) void ta_combine_kernel(float* __restrict__ out)
{
    __shared__ float4 acc2[16][16];

    const int b   = blockIdx.x >> 2;
    const int g   = blockIdx.x & 3;
    const int t   = threadIdx.x;
    const int ci  = t >> 4;       // 0..15
    const int d4l = t & 15;
    const int d4  = g * 16 + d4l; // float4 index in [0, 64)

    const float4* pa4 = reinterpret_cast<const float4*>(g_pa);

    float4 acc = make_float4(0.f, 0.f, 0.f, 0.f);
    #pragma unroll
    for (int i = 0; i < NCHUNK / 16; i++) {
        const int c = ci + 16 * i;
        const float wgt = g_w[b * NCHUNK + c];
        const float4 x = pa4[((size_t)(b * NCHUNK + c)) * (DD / 4) + d4];
        acc.x = fmaf(wgt, x.x, acc.x);
        acc.y = fmaf(wgt, x.y, acc.y);
        acc.z = fmaf(wgt, x.z, acc.z);
        acc.w = fmaf(wgt, x.w, acc.w);
    }
    acc2[ci][d4l] = acc;
    __syncthreads();

    // tree-reduce 16 chunk-lanes
    if (ci < 8) {
        float4 o = acc2[ci][d4l], q = acc2[ci + 8][d4l];
        o.x += q.x; o.y += q.y; o.z += q.z; o.w += q.w;
        acc2[ci][d4l] = o;
    }
    __syncthreads();
    if (ci < 4) {
        float4 o = acc2[ci][d4l], q = acc2[ci + 4][d4l];
        o.x += q.x; o.y += q.y; o.z += q.z; o.w += q.w;
        acc2[ci][d4l] = o;
    }
    __syncthreads();
    if (ci == 0) {
        float4 o = acc2[0][d4l];
        const float4 q1 = acc2[1][d4l];
        const float4 q2 = acc2[2][d4l];
        const float4 q3 = acc2[3][d4l];
        o.x += q1.x + q2.x + q3.x;
        o.y += q1.y + q2.y + q3.y;
        o.z += q1.z + q2.z + q3.z;
        o.w += q1.w + q2.w + q3.w;
        // out is [D, B]; this thread owns d = 4*d4 .. 4*d4+3
        const int d0 = d4 * 4;
        out[(d0 + 0) * BB + b] = o.x;
        out[(d0 + 1) * BB + b] = o.y;
        out[(d0 + 2) * BB + b] = o.z;
        out[(d0 + 3) * BB + b] = o.w;
    }
}

extern "C" void kernel_launch(void* const* d_in, const int* in_sizes, int n_in,
                              void* d_out, int out_size)
{
    const float* enc = (const float*)d_in[0];   // [B, S, D]
    const float* Ww  = (const float*)d_in[1];   // [1, D]
    // d_in[2] = We_b : scalar bias is softmax-invariant, dropped
    const float* ut  = (const float*)d_in[3];   // [1, 1]
    float* out = (float*)d_out;                 // [D, B]

    ta_partial_kernel<<<BB * NCHUNK, 256>>>(enc, Ww, ut);
    ta_ml_kernel<<<BB, 128>>>();
    ta_combine_kernel<<<BB * 4, 256>>>(out);
}

// round 5
// speedup vs baseline: 1.2519x; 1.0464x over previous
#include <cuda_runtime.h>
#include <cuda_bf16.h>
#include <math_constants.h>
#include <cstdint>

#define BB 64
#define SS 4096
#define DD 256
#define ROWS 16                       // rows per tile
#define TILES 8                       // tiles per CTA -> 128 rows per CTA
#define NCC (SS / (ROWS * TILES))     // 32 output chunks per batch
#define TILE_B (ROWS * DD * 4)        // 16 KB

// Scratch (allocation-free: __device__ globals)
__device__ float g_pm[BB * NCC];           // chunk running max
__device__ float g_pl[BB * NCC];           // chunk exp-sum
__device__ float g_pa[BB * NCC * DD];      // weighted partials (2 MB)

__device__ __forceinline__ uint32_t smem_u32(const void* p) {
    uint32_t a;
    asm("{ .reg .u64 t; cvta.to.shared.u64 t, %1; cvt.u32.u64 %0, t; }"
        : "=r"(a) : "l"(p));
    return a;
}

__device__ __forceinline__ void mbar_wait(uint32_t mbar, uint32_t parity) {
    asm volatile(
        "{\n\t"
        ".reg .pred P;\n\t"
        "WAIT_%=:\n\t"
        "mbarrier.try_wait.parity.acquire.cta.shared::cta.b64 P, [%0], %1, 0x989680;\n\t"
        "@P bra.uni DONE_%=;\n\t"
        "bra.uni WAIT_%=;\n\t"
        "DONE_%=:\n\t"
        "}" :: "r"(mbar), "r"(parity) : "memory");
}

__device__ __forceinline__ void tma_tile(uint32_t mb, uint32_t sdst, const float* src) {
    asm volatile("mbarrier.arrive.expect_tx.shared.b64 _, [%0], %1;"
                 :: "r"(mb), "r"((uint32_t)TILE_B) : "memory");
    asm volatile(
        "cp.async.bulk.shared::cta.global.mbarrier::complete_tx::bytes "
        "[%0], [%1], %2, [%3];"
        :: "r"(sdst), "l"(src), "r"((uint32_t)TILE_B), "r"(mb) : "memory");
}

// ---------------------------------------------------------------------------
// Kernel 1: grid = BB * NCC = 2048 CTAs, 256 threads.
//   Each CTA streams 8 x 16-row tiles through a 2-deep TMA pipeline and keeps
//   an online-softmax accumulator (acc[d] per thread, block-uniform M/L).
// ---------------------------------------------------------------------------
__global__ __launch_bounds__(256) void ta_partial_kernel(
    const float* __restrict__ enc,   // [B, S, D]
    const float* __restrict__ Ww,    // [1, D]
    const float* __restrict__ ut)    // [1, 1]
{
    __shared__ __align__(128) float sx[2][ROWS][DD];   // 2 x 16 KB
    __shared__ float sraw[ROWS];
    __shared__ float ssc[ROWS];
    __shared__ float s_scale;
    __shared__ __align__(8) unsigned long long mbar[2];

    const int blk  = blockIdx.x;
    const int b    = blk >> 5;        // / NCC
    const int cc   = blk & (NCC - 1);
    const int tid  = threadIdx.x;
    const int w    = tid >> 5;
    const int lane = tid & 31;

    const uint32_t mb0 = smem_u32(&mbar[0]);
    const uint32_t mb1 = smem_u32(&mbar[1]);
    const uint32_t sd0 = smem_u32(&sx[0][0][0]);
    const uint32_t sd1 = smem_u32(&sx[1][0][0]);

    if (tid == 0) {
        asm volatile("mbarrier.init.shared.b64 [%0], 1;" :: "r"(mb0) : "memory");
        asm volatile("mbarrier.init.shared.b64 [%0], 1;" :: "r"(mb1) : "memory");
    }
    __syncthreads();

    const float* src0 = enc + ((size_t)b * SS + (size_t)cc * ROWS * TILES) * DD;

    if (tid == 0) {
        tma_tile(mb0, sd0, src0);
        tma_tile(mb1, sd1, src0 + ROWS * DD);
    }

    const float u = ut[0];
    const float4 w0 = reinterpret_cast<const float4*>(Ww)[lane];
    const float4 w1 = reinterpret_cast<const float4*>(Ww)[lane + 32];

    float acc = 0.f;                // per-thread column d = tid
    float M_r = -1e30f, L_r = 0.f;  // meaningful in warp 0, lanes < 16

    #pragma unroll
    for (int k = 0; k < TILES; k++) {
        const int buf = k & 1;
        const uint32_t mb = buf ? mb1 : mb0;
        mbar_wait(mb, (k >> 1) & 1);

        // ---- scores: warp w handles rows w and w+8 ----
        const float4* t4 = reinterpret_cast<const float4*>(&sx[buf][0][0]);
        const float4 a00 = t4[w * 64 + lane];
        const float4 a01 = t4[w * 64 + lane + 32];
        const float4 a10 = t4[(w + 8) * 64 + lane];
        const float4 a11 = t4[(w + 8) * 64 + lane + 32];

        float p0x = a00.x * w0.x, p0y = a00.y * w0.y;
        float p1x = a10.x * w0.x, p1y = a10.y * w0.y;
        p0x = fmaf(a00.z, w0.z, p0x); p0y = fmaf(a00.w, w0.w, p0y);
        p1x = fmaf(a10.z, w0.z, p1x); p1y = fmaf(a10.w, w0.w, p1y);
        p0x = fmaf(a01.x, w1.x, p0x); p0y = fmaf(a01.y, w1.y, p0y);
        p1x = fmaf(a11.x, w1.x, p1x); p1y = fmaf(a11.y, w1.y, p1y);
        p0x = fmaf(a01.z, w1.z, p0x); p0y = fmaf(a01.w, w1.w, p0y);
        p1x = fmaf(a11.z, w1.z, p1x); p1y = fmaf(a11.w, w1.w, p1y);
        float p0 = p0x + p0y;
        float p1 = p1x + p1y;
        #pragma unroll
        for (int off = 16; off > 0; off >>= 1) {
            p0 += __shfl_xor_sync(0xffffffffu, p0, off);
            p1 += __shfl_xor_sync(0xffffffffu, p1, off);
        }
        if (lane == 0) { sraw[w] = p0; sraw[w + 8] = p1; }
        __syncthreads();

        // ---- online softmax update (warp 0, lanes < 16) ----
        if (w == 0 && lane < 16) {
            const float v = u * sraw[lane];
            float m = v;
            #pragma unroll
            for (int off = 8; off > 0; off >>= 1)
                m = fmaxf(m, __shfl_xor_sync(0x0000ffffu, m, off));
            const float newM   = fmaxf(M_r, m);
            const float sc_old = __expf(M_r - newM);
            const float e      = __expf(v - newM);
            float l = e;
            #pragma unroll
            for (int off = 8; off > 0; off >>= 1)
                l += __shfl_xor_sync(0x0000ffffu, l, off);
            L_r = L_r * sc_old + l;
            M_r = newM;
            ssc[lane] = e;
            if (lane == 0) s_scale = sc_old;
        }
        __syncthreads();

        // ---- rescale + accumulate this tile ----
        acc *= s_scale;
        #pragma unroll
        for (int s = 0; s < ROWS; s++)
            acc = fmaf(ssc[s], sx[buf][s][tid], acc);
        __syncthreads();   // everyone done with sx[buf] & ssc before reuse

        if (tid == 0 && k + 2 < TILES)
            tma_tile(mb, buf ? sd1 : sd0, src0 + (size_t)(k + 2) * ROWS * DD);
    }

    g_pa[((size_t)(b * NCC + cc)) * DD + tid] = acc;
    if (tid == 0) {
        g_pm[b * NCC + cc] = M_r;
        g_pl[b * NCC + cc] = L_r;
    }
}

// ---------------------------------------------------------------------------
// Kernel 2: grid = BB * 4. Block (b, g) covers d in [g*64, g*64+64) as float4.
//   Warp 0 redundantly computes M, L, weights from 32 chunk (m,l) pairs
//   (L2-resident), then 256 threads stream the 8 KB of partials.
// ---------------------------------------------------------------------------
__global__ __launch_bounds__(256) void ta_combine_kernel(float* __restrict__ out)
{
    __shared__ float wsc[NCC];
    __shared__ float4 acc2[16][16];

    const int b   = blockIdx.x >> 2;
    const int g   = blockIdx.x & 3;
    const int t   = threadIdx.x;
    const int ci  = t >> 4;       // 0..15
    const int d4l = t & 15;
    const int d4  = g * 16 + d4l; // float4 index in [0, 64)

    if (t < NCC) {
        const float m = g_pm[b * NCC + t];
        const float l = g_pl[b * NCC + t];
        float M = m;
        #pragma unroll
        for (int off = 16; off > 0; off >>= 1)
            M = fmaxf(M, __shfl_xor_sync(0xffffffffu, M, off));
        const float e = __expf(m - M);
        float L = e * l;
        #pragma unroll
        for (int off = 16; off > 0; off >>= 1)
            L += __shfl_xor_sync(0xffffffffu, L, off);
        wsc[t] = e / L;
    }
    __syncthreads();

    const float4* pa4 = reinterpret_cast<const float4*>(g_pa);

    float4 acc = make_float4(0.f, 0.f, 0.f, 0.f);
    #pragma unroll
    for (int i = 0; i < NCC / 16; i++) {
        const int c = ci + 16 * i;
        const float wgt = wsc[c];
        const float4 x = pa4[((size_t)(b * NCC + c)) * (DD / 4) + d4];
        acc.x = fmaf(wgt, x.x, acc.x);
        acc.y = fmaf(wgt, x.y, acc.y);
        acc.z = fmaf(wgt, x.z, acc.z);
        acc.w = fmaf(wgt, x.w, acc.w);
    }
    acc2[ci][d4l] = acc;
    __syncthreads();

    if (ci < 8) {
        float4 o = acc2[ci][d4l], q = acc2[ci + 8][d4l];
        o.x += q.x; o.y += q.y; o.z += q.z; o.w += q.w;
        acc2[ci][d4l] = o;
    }
    __syncthreads();
    if (ci < 4) {
        float4 o = acc2[ci][d4l], q = acc2[ci + 4][d4l];
        o.x += q.x; o.y += q.y; o.z += q.z; o.w += q.w;
        acc2[ci][d4l] = o;
    }
    __syncthreads();
    if (ci == 0) {
        float4 o = acc2[0][d4l];
        const float4 q1 = acc2[1][d4l];
        const float4 q2 = acc2[2][d4l];
        const float4 q3 = acc2[3][d4l];
        o.x += q1.x + q2.x + q3.x;
        o.y += q1.y + q2.y + q3.y;
        o.z += q1.z + q2.z + q3.z;
        o.w += q1.w + q2.w + q3.w;
        const int d0 = d4 * 4;       // out is [D, B]
        out[(d0 + 0) * BB + b] = o.x;
        out[(d0 + 1) * BB + b] = o.y;
        out[(d0 + 2) * BB + b] = o.z;
        out[(d0 + 3) * BB + b] = o.w;
    }
}

extern "C" void kernel_launch(void* const* d_in, const int* in_sizes, int n_in,
                              void* d_out, int out_size)
{
    const float* enc = (const float*)d_in[0];   // [B, S, D]
    const float* Ww  = (const float*)d_in[1];   // [1, D]
    // d_in[2] = We_b : scalar bias is softmax-invariant, dropped
    const float* ut  = (const float*)d_in[3];   // [1, 1]
    float* out = (float*)d_out;                 // [D, B]

    ta_partial_kernel<<<BB * NCC, 256>>>(enc, Ww, ut);
    ta_combine_kernel<<<BB * 4, 256>>>(out);
}